// round 16
// baseline (speedup 1.0000x reference)
#include <cuda_runtime.h>
#include <cstdint>

#define BATCH 2
#define SEQ 2048
#define HID 2048
#define NH 32
#define NKV 8
#define HD 64
#define HALF 32
#define GK 2048
#define CHUNK 32
#define NCHUNK (GK / CHUNK)
#define NQKV 3072

// ---------------- scratch (static device globals; no allocation) -------------
__device__ float g_q[BATCH * NH * SEQ * HD];     // roped, scaled  [B,H,S,D]
__device__ float g_k[BATCH * NKV * SEQ * HD];    // roped          [B,KV,S,D]
__device__ float g_vt[BATCH * NKV * HD * SEQ];   // TRANSPOSED     [B,KV,D,S]
__device__ float g_ao[BATCH * SEQ * HID];        // attn out [B,S,H*D]
__device__ float g_wqkvT[NQKV * HID];
__device__ float g_woT[HID * HID];

// ---------------- helpers ----------------------------------------------------
__device__ __forceinline__ uint32_t f2h2(float lo, float hi) {
    uint32_t d;
    asm("cvt.rn.f16x2.f32 %0, %1, %2;" : "=r"(d) : "f"(hi), "f"(lo));
    return d;
}
__device__ __forceinline__ float ex2(float x) {
    float r;
    asm("ex2.approx.f32 %0, %1;" : "=f"(r) : "f"(x));
    return r;
}
__device__ __forceinline__ uint32_t smem_u32(const void* p) {
    return (uint32_t)__cvta_generic_to_shared(p);
}

#define MMA_F16(d, a, b)                                                       \
    asm volatile("mma.sync.aligned.m16n8k16.row.col.f32.f16.f16.f32 "          \
        "{%0,%1,%2,%3}, {%4,%5,%6,%7}, {%8,%9}, {%0,%1,%2,%3};"                \
        : "+f"((d)[0]), "+f"((d)[1]), "+f"((d)[2]), "+f"((d)[3])               \
        : "r"((a)[0]), "r"((a)[1]), "r"((a)[2]), "r"((a)[3]),                  \
          "r"((b)[0]), "r"((b)[1]))

#define LDSM_X4(r0, r1, r2, r3, addr)                                          \
    asm volatile("ldmatrix.sync.aligned.m8n8.x4.shared.b16 {%0,%1,%2,%3}, [%4];" \
        : "=r"(r0), "=r"(r1), "=r"(r2), "=r"(r3) : "r"(addr))

// ---------------- weight transpose: out[C][R] = in[R][C] ---------------------
__global__ void transpose_kernel(const float* __restrict__ in, float* __restrict__ out,
                                 int R, int C) {
    __shared__ float t[32][33];
    int bx = blockIdx.x * 32, by = blockIdx.y * 32;
#pragma unroll
    for (int j = 0; j < 32; j += 8)
        t[threadIdx.y + j][threadIdx.x] =
            in[(size_t)(by + threadIdx.y + j) * C + bx + threadIdx.x];
    __syncthreads();
#pragma unroll
    for (int j = 0; j < 32; j += 8)
        out[(size_t)(bx + threadIdx.y + j) * R + by + threadIdx.x] =
            t[threadIdx.x][threadIdx.y + j];
}

// ---------------- fp16 GEMM mainloop (ldmatrix fragments) ---------------------
#define WPITCH 20
#define TILE_W (128 * WPITCH)
#define GEMM_SMEM (2 * 2 * TILE_W * 4)

#define GEMM_MAINLOOP(Aptr, Bptr)                                              \
    float acc[4][4][4];                                                        \
    _Pragma("unroll")                                                          \
    for (int mi = 0; mi < 4; mi++)                                             \
        _Pragma("unroll")                                                      \
        for (int ni = 0; ni < 4; ni++)                                         \
            _Pragma("unroll")                                                  \
            for (int e = 0; e < 4; e++) acc[mi][ni][e] = 0.0f;                 \
    uint32_t sbase = smem_u32(smem);                                           \
    int rsel = (lane & 7) + 8 * ((lane >> 3) & 1);                             \
    int ksel = (lane >> 4) << 2;                                               \
    float4 av[4], bv[4];                                                       \
    _Pragma("unroll")                                                          \
    for (int p = 0; p < 4; p++) {                                              \
        int row = p * 32 + lrow;                                               \
        av[p] = *(const float4*)(Aptr + (size_t)row * GK + lc4);               \
        bv[p] = *(const float4*)(Bptr + (size_t)row * GK + lc4);               \
    }                                                                          \
    {                                                                          \
        uint32_t* As = smem;                                                   \
        uint32_t* Bs = smem + TILE_W;                                          \
        _Pragma("unroll")                                                      \
        for (int p = 0; p < 4; p++) {                                          \
            int row = p * 32 + lrow;                                           \
            uint32_t* ap = As + row * WPITCH + (lc4 >> 1);                     \
            ap[0] = f2h2(av[p].x, av[p].y);                                    \
            ap[1] = f2h2(av[p].z, av[p].w);                                    \
            uint32_t* bp = Bs + row * WPITCH + (lc4 >> 1);                     \
            bp[0] = f2h2(bv[p].x, bv[p].y);                                    \
            bp[1] = f2h2(bv[p].z, bv[p].w);                                    \
        }                                                                      \
    }                                                                          \
    __syncthreads();                                                           \
    for (int i = 0; i < NCHUNK; i++) {                                         \
        if (i + 1 < NCHUNK) {                                                  \
            int k0 = (i + 1) * CHUNK;                                          \
            _Pragma("unroll")                                                  \
            for (int p = 0; p < 4; p++) {                                      \
                int row = p * 32 + lrow;                                       \
                av[p] = *(const float4*)(Aptr + (size_t)row * GK + k0 + lc4);  \
                bv[p] = *(const float4*)(Bptr + (size_t)row * GK + k0 + lc4);  \
            }                                                                  \
        }                                                                      \
        {                                                                      \
            uint32_t abase = sbase + ((i & 1) * 2 * TILE_W) * 4;               \
            uint32_t bbase = abase + TILE_W * 4;                               \
            _Pragma("unroll")                                                  \
            for (int ks = 0; ks < 2; ks++) {                                   \
                int kw = ks * 8 + ksel;                                        \
                uint32_t afr[4][4];                                            \
                _Pragma("unroll")                                              \
                for (int mi = 0; mi < 4; mi++)                                 \
                    LDSM_X4(afr[mi][0], afr[mi][1], afr[mi][2], afr[mi][3],    \
                            abase + ((wm + mi * 16 + rsel) * WPITCH + kw) * 4);\
                uint32_t bfr[4][2];                                            \
                LDSM_X4(bfr[0][0], bfr[1][0], bfr[0][1], bfr[1][1],            \
                        bbase + ((wn + rsel) * WPITCH + kw) * 4);              \
                LDSM_X4(bfr[2][0], bfr[3][0], bfr[2][1], bfr[3][1],            \
                        bbase + ((wn + 16 + rsel) * WPITCH + kw) * 4);         \
                _Pragma("unroll")                                              \
                for (int mi = 0; mi < 4; mi++)                                 \
                    _Pragma("unroll")                                          \
                    for (int ni = 0; ni < 4; ni++)                             \
                        MMA_F16(acc[mi][ni], afr[mi], bfr[ni]);                \
            }                                                                  \
        }                                                                      \
        if (i + 1 < NCHUNK) {                                                  \
            __syncthreads();                                                   \
            uint32_t* As = smem + ((i + 1) & 1) * 2 * TILE_W;                  \
            uint32_t* Bs = As + TILE_W;                                        \
            _Pragma("unroll")                                                  \
            for (int p = 0; p < 4; p++) {                                      \
                int row = p * 32 + lrow;                                       \
                uint32_t* ap = As + row * WPITCH + (lc4 >> 1);                 \
                ap[0] = f2h2(av[p].x, av[p].y);                                \
                ap[1] = f2h2(av[p].z, av[p].w);                                \
                uint32_t* bp = Bs + row * WPITCH + (lc4 >> 1);                 \
                bp[0] = f2h2(bv[p].x, bv[p].y);                                \
                bp[1] = f2h2(bv[p].z, bv[p].w);                                \
            }                                                                  \
            __syncthreads();                                                   \
        }                                                                      \
    }

// ---------------- plain GEMM (output projection) ------------------------------
__global__ __launch_bounds__(256)
void f16_gemm(const float* __restrict__ A, const float* __restrict__ BT,
              float* __restrict__ C, int N) {
    extern __shared__ uint32_t smem[];
    int tid = threadIdx.x;
    int w = tid >> 5, lane = tid & 31;
    int g = lane >> 2, t = lane & 3;
    int wm = (w >> 2) * 64, wn = (w & 3) * 32;
    int bm = blockIdx.y * 128, bn = blockIdx.x * 128;
    const float* Ab = A + (size_t)bm * GK;
    const float* Bb = BT + (size_t)bn * GK;
    int lrow = tid >> 3, lc4 = (tid & 7) << 2;

    GEMM_MAINLOOP(Ab, Bb)

#pragma unroll
    for (int mi = 0; mi < 4; mi++) {
#pragma unroll
        for (int ni = 0; ni < 4; ni++) {
            int r0 = bm + wm + mi * 16 + g;
            int c0 = bn + wn + ni * 8 + t * 2;
            *(float2*)(C + (size_t)r0 * N + c0) =
                make_float2(acc[mi][ni][0], acc[mi][ni][1]);
            *(float2*)(C + (size_t)(r0 + 8) * N + c0) =
                make_float2(acc[mi][ni][2], acc[mi][ni][3]);
        }
    }
}

// ---------------- fused QKV GEMM + RoPE epilogue (V written transposed) -------
#define QSCALE (0.125f * 1.44269504088896f)   // 1/sqrt(64) * log2(e)

__device__ __forceinline__ void qkv_write_pair(
    float* gq, float* gk, float* gvt,
    const float* __restrict__ fc, const float* __restrict__ fs,
    int r, int c, float e0, float e1) {
    int b = r >> 11, s = r & 2047;
    if (c < HID) {
        int h = c >> 6, d = c & 63, p = d >> 1;
        float cs = fc[s * HALF + p], sn = fs[s * HALF + p];
        *(float2*)(gq + ((size_t)(b * NH + h) * SEQ + s) * HD + d) =
            make_float2((e0 * cs - e1 * sn) * QSCALE,
                        (e0 * sn + e1 * cs) * QSCALE);
    } else if (c < HID + NKV * HD) {
        int cc = c - HID;
        int kvh = cc >> 6, d = cc & 63, p = d >> 1;
        float cs = fc[s * HALF + p], sn = fs[s * HALF + p];
        *(float2*)(gk + ((size_t)(b * NKV + kvh) * SEQ + s) * HD + d) =
            make_float2(e0 * cs - e1 * sn, e0 * sn + e1 * cs);
    } else {                                  // V: transposed [B,KV,D,S]
        int cc = c - HID - NKV * HD;
        int kvh = cc >> 6, d = cc & 63;
        size_t base = ((size_t)(b * NKV + kvh) * HD + d) * SEQ + s;
        gvt[base] = e0;
        gvt[base + SEQ] = e1;                 // d+1 row
    }
}

__global__ __launch_bounds__(256)
void qkv_rope_gemm(const float* __restrict__ A, const float* __restrict__ BT,
                   float* __restrict__ gq, float* __restrict__ gk,
                   float* __restrict__ gvt,
                   const float* __restrict__ fc, const float* __restrict__ fs) {
    extern __shared__ uint32_t smem[];
    int tid = threadIdx.x;
    int w = tid >> 5, lane = tid & 31;
    int g = lane >> 2, t = lane & 3;
    int wm = (w >> 2) * 64, wn = (w & 3) * 32;
    int bm = blockIdx.y * 128, bn = blockIdx.x * 128;
    const float* Ab = A + (size_t)bm * GK;
    const float* Bb = BT + (size_t)bn * GK;
    int lrow = tid >> 3, lc4 = (tid & 7) << 2;

    GEMM_MAINLOOP(Ab, Bb)

#pragma unroll
    for (int mi = 0; mi < 4; mi++) {
#pragma unroll
        for (int ni = 0; ni < 4; ni++) {
            int r0 = bm + wm + mi * 16 + g;
            int c0 = bn + wn + ni * 8 + t * 2;
            qkv_write_pair(gq, gk, gvt, fc, fs, r0, c0,
                           acc[mi][ni][0], acc[mi][ni][1]);
            qkv_write_pair(gq, gk, gvt, fc, fs, r0 + 8, c0,
                           acc[mi][ni][2], acc[mi][ni][3]);
        }
    }
}

// ---------------- fp16 tensor-core flash attention (ldmatrix) -----------------
// CTA: 128 q-rows x one (b,h), 8 warps x 16 rows, K-tile = 64 keys.
#define AP 36
#define KS_OFF 0
#define VS_OFF (64 * AP)
#define PS_OFF (2 * 64 * AP)
#define ATTN_SMEM ((2 * 64 * AP + 8 * 16 * AP) * 4)   // 36864 B

__global__ __launch_bounds__(256, 2)
void attn_f16_kernel(const float* __restrict__ Q, const float* __restrict__ K,
                     const float* __restrict__ Vt, float* __restrict__ O) {
    extern __shared__ uint32_t sm[];
    uint32_t* Ks = sm + KS_OFF;
    uint32_t* Vs = sm + VS_OFF;

    int tid = threadIdx.x;
    int w = tid >> 5, lane = tid & 31;
    int g = lane >> 2, t = lane & 3;
    int qt = gridDim.x - 1 - blockIdx.x;     // longest first
    int bh = blockIdx.y;
    int b = bh >> 5, h = bh & 31;
    int kvh = h >> 2;
    int q0 = qt * 128;
    int qrow = w * 16;

    uint32_t smbase = smem_u32(sm);
    uint32_t ksbase = smbase + KS_OFF * 4;
    uint32_t vsbase = smbase + VS_OFF * 4;
    uint32_t pwbase = smbase + (PS_OFF + w * 16 * AP) * 4;
    uint32_t* Pw = sm + PS_OFF + w * 16 * AP;

    int rsel = (lane & 7) + 8 * ((lane >> 3) & 1);
    int ksel = (lane >> 4) << 2;

    const float* Qb = Q + ((size_t)(b * NH + h) * SEQ + q0) * HD;
    const float* Kb = K + (size_t)(b * NKV + kvh) * SEQ * HD;
    const float* Vb = Vt + (size_t)(b * NKV + kvh) * HD * SEQ;

    // Q fragments (m16n8k16 A) -> registers once
    uint32_t qf[4][4];
#pragma unroll
    for (int ks = 0; ks < 4; ks++) {
        int d0 = ks * 16 + 2 * t;
        float2 x0 = *(const float2*)(Qb + (qrow + g) * HD + d0);
        float2 x1 = *(const float2*)(Qb + (qrow + 8 + g) * HD + d0);
        float2 x2 = *(const float2*)(Qb + (qrow + g) * HD + d0 + 8);
        float2 x3 = *(const float2*)(Qb + (qrow + 8 + g) * HD + d0 + 8);
        qf[ks][0] = f2h2(x0.x, x0.y);
        qf[ks][1] = f2h2(x1.x, x1.y);
        qf[ks][2] = f2h2(x2.x, x2.y);
        qf[ks][3] = f2h2(x3.x, x3.y);
    }

    float oacc[8][4];
#pragma unroll
    for (int ni = 0; ni < 8; ni++)
#pragma unroll
        for (int e = 0; e < 4; e++) oacc[ni][e] = 0.0f;
    float m0 = -1e30f, m1 = -1e30f, l0 = 0.0f, l1 = 0.0f;   // l: per-thread partial

    int ktmax = (q0 >> 6) + 1;
    int ldrow = tid >> 4;              // 0..15
    int ldc4 = (tid & 15) << 2;        // 0..60 step 4

    for (int kt = 0; kt <= ktmax; kt++) {
        const float* Kp = Kb + (size_t)kt * 64 * HD;
        const float* Vp = Vb + (size_t)kt * 64;
        __syncthreads();   // previous tile consumed

        // ---- stage K [key][d] and V^T [d][key] as packed halves ----
#pragma unroll
        for (int p = 0; p < 4; p++) {
            int r = p * 16 + ldrow;
            float4 kv = *(const float4*)(Kp + (size_t)r * HD + ldc4);
            uint32_t* kp_ = Ks + r * AP + (ldc4 >> 1);
            kp_[0] = f2h2(kv.x, kv.y);
            kp_[1] = f2h2(kv.z, kv.w);
            float4 vv = *(const float4*)(Vp + (size_t)r * SEQ + ldc4);
            uint32_t* vp_ = Vs + r * AP + (ldc4 >> 1);
            vp_[0] = f2h2(vv.x, vv.y);
            vp_[1] = f2h2(vv.z, vv.w);
        }
        __syncthreads();

        // ---- S = Q K^T  (k-dim = d, 4 steps of 16) ----
        float sa[8][4];
#pragma unroll
        for (int ni = 0; ni < 8; ni++)
#pragma unroll
            for (int e = 0; e < 4; e++) sa[ni][e] = 0.0f;
#pragma unroll
        for (int ks = 0; ks < 4; ks++) {
            int kw = ks * 8 + ksel;
            uint32_t kf[8][2];
#pragma unroll
            for (int n2 = 0; n2 < 4; n2++)
                LDSM_X4(kf[2 * n2][0], kf[2 * n2 + 1][0],
                        kf[2 * n2][1], kf[2 * n2 + 1][1],
                        ksbase + ((n2 * 16 + rsel) * AP + kw) * 4);
#pragma unroll
            for (int ni = 0; ni < 8; ni++)
                MMA_F16(sa[ni], qf[ks], kf[ni]);
        }

        // ---- causal mask ----
        int r0 = q0 + qrow + g, r1 = r0 + 8;
        if (kt * 64 + 63 > r0) {
            int cb = kt * 64;
#pragma unroll
            for (int ni = 0; ni < 8; ni++) {
                int c0 = cb + ni * 8 + 2 * t, c1 = c0 + 1;
                if (c0 > r0) sa[ni][0] = -1e30f;
                if (c1 > r0) sa[ni][1] = -1e30f;
                if (c0 > r1) sa[ni][2] = -1e30f;
                if (c1 > r1) sa[ni][3] = -1e30f;
            }
        }

        // ---- online softmax (log2 domain; per-thread partial l) ----
        float mx0 = -1e30f, mx1 = -1e30f;
#pragma unroll
        for (int ni = 0; ni < 8; ni++) {
            mx0 = fmaxf(mx0, fmaxf(sa[ni][0], sa[ni][1]));
            mx1 = fmaxf(mx1, fmaxf(sa[ni][2], sa[ni][3]));
        }
        mx0 = fmaxf(mx0, __shfl_xor_sync(0xffffffffu, mx0, 1));
        mx0 = fmaxf(mx0, __shfl_xor_sync(0xffffffffu, mx0, 2));
        mx1 = fmaxf(mx1, __shfl_xor_sync(0xffffffffu, mx1, 1));
        mx1 = fmaxf(mx1, __shfl_xor_sync(0xffffffffu, mx1, 2));
        float mn0 = fmaxf(m0, mx0), mn1 = fmaxf(m1, mx1);
        float sc0 = ex2(m0 - mn0), sc1 = ex2(m1 - mn1);
        m0 = mn0; m1 = mn1;
        float sum0 = 0.0f, sum1 = 0.0f;
#pragma unroll
        for (int ni = 0; ni < 8; ni++) {
            sa[ni][0] = ex2(sa[ni][0] - mn0); sum0 += sa[ni][0];
            sa[ni][1] = ex2(sa[ni][1] - mn0); sum0 += sa[ni][1];
            sa[ni][2] = ex2(sa[ni][2] - mn1); sum1 += sa[ni][2];
            sa[ni][3] = ex2(sa[ni][3] - mn1); sum1 += sa[ni][3];
        }
        l0 = l0 * sc0 + sum0;             // per-thread partial; reduced at end
        l1 = l1 * sc1 + sum1;
#pragma unroll
        for (int ni = 0; ni < 8; ni++) {
            oacc[ni][0] *= sc0; oacc[ni][1] *= sc0;
            oacc[ni][2] *= sc1; oacc[ni][3] *= sc1;
        }

        // ---- P -> packed halves [16 rows][32 words], per-warp region ----
#pragma unroll
        for (int ni = 0; ni < 8; ni++) {
            int c = 4 * ni + t;
            Pw[g * AP + c]       = f2h2(sa[ni][0], sa[ni][1]);
            Pw[(g + 8) * AP + c] = f2h2(sa[ni][2], sa[ni][3]);
        }
        __syncwarp();

        // ---- O += P V  (k-dim = key, 4 steps of 16) ----
#pragma unroll
        for (int ks = 0; ks < 4; ks++) {
            int kw = ks * 8 + ksel;
            uint32_t a[4];
            LDSM_X4(a[0], a[1], a[2], a[3], pwbase + (rsel * AP + kw) * 4);
            uint32_t vf[8][2];
#pragma unroll
            for (int n2 = 0; n2 < 4; n2++)
                LDSM_X4(vf[2 * n2][0], vf[2 * n2 + 1][0],
                        vf[2 * n2][1], vf[2 * n2 + 1][1],
                        vsbase + ((n2 * 16 + rsel) * AP + kw) * 4);
#pragma unroll
            for (int ni = 0; ni < 8; ni++)
                MMA_F16(oacc[ni], a, vf[ni]);
        }
        __syncwarp();
    }

    // ---- final l reduction + normalize + write [B,S,H*D] ----
    l0 += __shfl_xor_sync(0xffffffffu, l0, 1);
    l0 += __shfl_xor_sync(0xffffffffu, l0, 2);
    l1 += __shfl_xor_sync(0xffffffffu, l1, 1);
    l1 += __shfl_xor_sync(0xffffffffu, l1, 2);
    float rl0 = 1.0f / l0, rl1 = 1.0f / l1;
    int r0 = q0 + qrow + g, r1 = r0 + 8;
#pragma unroll
    for (int ni = 0; ni < 8; ni++) {
        int col = ni * 8 + 2 * t;
        *(float2*)(O + ((size_t)(b * SEQ + r0) * NH + h) * HD + col) =
            make_float2(oacc[ni][0] * rl0, oacc[ni][1] * rl0);
        *(float2*)(O + ((size_t)(b * SEQ + r1) * NH + h) * HD + col) =
            make_float2(oacc[ni][2] * rl1, oacc[ni][3] * rl1);
    }
}

// ---------------- launcher ---------------------------------------------------
extern "C" void kernel_launch(void* const* d_in, const int* in_sizes, int n_in,
                              void* d_out, int out_size) {
    const float* x  = (const float*)d_in[0];
    const float* wq = (const float*)d_in[1];
    const float* wk = (const float*)d_in[2];
    const float* wv = (const float*)d_in[3];
    const float* wo = (const float*)d_in[4];
    const float* fc = (const float*)d_in[5];
    const float* fs = (const float*)d_in[6];
    float* out = (float*)d_out;

    float *q, *k, *vt, *ao, *wqkvT, *woT;
    cudaGetSymbolAddress((void**)&q,  g_q);
    cudaGetSymbolAddress((void**)&k,  g_k);
    cudaGetSymbolAddress((void**)&vt, g_vt);
    cudaGetSymbolAddress((void**)&ao, g_ao);
    cudaGetSymbolAddress((void**)&wqkvT, g_wqkvT);
    cudaGetSymbolAddress((void**)&woT, g_woT);

    const int M = BATCH * SEQ;  // 4096

    transpose_kernel<<<dim3(HID / 32, HID / 32), dim3(32, 8)>>>(wq, wqkvT, HID, HID);
    transpose_kernel<<<dim3((NKV * HD) / 32, HID / 32), dim3(32, 8)>>>(
        wk, wqkvT + (size_t)HID * HID, HID, NKV * HD);
    transpose_kernel<<<dim3((NKV * HD) / 32, HID / 32), dim3(32, 8)>>>(
        wv, wqkvT + (size_t)(HID + NKV * HD) * HID, HID, NKV * HD);
    transpose_kernel<<<dim3(HID / 32, HID / 32), dim3(32, 8)>>>(wo, woT, HID, HID);

    cudaFuncSetAttribute(qkv_rope_gemm, cudaFuncAttributeMaxDynamicSharedMemorySize,
                         GEMM_SMEM);
    cudaFuncSetAttribute(f16_gemm, cudaFuncAttributeMaxDynamicSharedMemorySize,
                         GEMM_SMEM);

    // fused QKV projection + RoPE epilogue (V written transposed)
    qkv_rope_gemm<<<dim3(NQKV / 128, M / 128), 256, GEMM_SMEM>>>(
        x, wqkvT, q, k, vt, fc, fs);

    // fp16 tensor-core flash attention (ldmatrix fragments)
    cudaFuncSetAttribute(attn_f16_kernel, cudaFuncAttributeMaxDynamicSharedMemorySize,
                         ATTN_SMEM);
    attn_f16_kernel<<<dim3(SEQ / 128, BATCH * NH), 256, ATTN_SMEM>>>(q, k, vt, ao);

    // output projection
    f16_gemm<<<dim3(HID / 128, M / 128), 256, GEMM_SMEM>>>(ao, woT, out, HID);
}

// round 17
// speedup vs baseline: 1.2299x; 1.2299x over previous
#include <cuda_runtime.h>
#include <cuda_fp16.h>
#include <cstdint>

#define BATCH 2
#define SEQ 2048
#define HID 2048
#define NH 32
#define NKV 8
#define HD 64
#define HALF 32
#define GK 2048
#define CHUNK 32
#define NCHUNK (GK / CHUNK)
#define NQKV 3072

// ---------------- scratch (static device globals; no allocation) -------------
__device__ __half g_q[BATCH * NH * SEQ * HD];    // roped, scaled, fp16 [B,H,S,D]
__device__ __half g_k[BATCH * NKV * SEQ * HD];   // roped, fp16        [B,KV,S,D]
__device__ __half g_vt[BATCH * NKV * HD * SEQ];  // fp16 TRANSPOSED    [B,KV,D,S]
__device__ float g_ao[BATCH * SEQ * HID];        // attn out fp32 [B,S,H*D]
__device__ float g_wqkvT[NQKV * HID];
__device__ float g_woT[HID * HID];

// ---------------- helpers ----------------------------------------------------
__device__ __forceinline__ uint32_t f2h2(float lo, float hi) {
    uint32_t d;
    asm("cvt.rn.f16x2.f32 %0, %1, %2;" : "=r"(d) : "f"(hi), "f"(lo));
    return d;
}
__device__ __forceinline__ float ex2(float x) {
    float r;
    asm("ex2.approx.f32 %0, %1;" : "=f"(r) : "f"(x));
    return r;
}
__device__ __forceinline__ uint32_t smem_u32(const void* p) {
    return (uint32_t)__cvta_generic_to_shared(p);
}

#define MMA_F16(d, a, b)                                                       \
    asm volatile("mma.sync.aligned.m16n8k16.row.col.f32.f16.f16.f32 "          \
        "{%0,%1,%2,%3}, {%4,%5,%6,%7}, {%8,%9}, {%0,%1,%2,%3};"                \
        : "+f"((d)[0]), "+f"((d)[1]), "+f"((d)[2]), "+f"((d)[3])               \
        : "r"((a)[0]), "r"((a)[1]), "r"((a)[2]), "r"((a)[3]),                  \
          "r"((b)[0]), "r"((b)[1]))

#define CP_ASYNC16(dst, src)                                                   \
    asm volatile("cp.async.cg.shared.global [%0], [%1], 16;"                   \
        :: "r"(dst), "l"(src))
#define CP_COMMIT() asm volatile("cp.async.commit_group;" ::: "memory")
#define CP_WAIT(n)  asm volatile("cp.async.wait_group %0;" :: "n"(n) : "memory")

// ---------------- weight transpose: out[C][R] = in[R][C] ---------------------
__global__ void transpose_kernel(const float* __restrict__ in, float* __restrict__ out,
                                 int R, int C) {
    __shared__ float t[32][33];
    int bx = blockIdx.x * 32, by = blockIdx.y * 32;
#pragma unroll
    for (int j = 0; j < 32; j += 8)
        t[threadIdx.y + j][threadIdx.x] =
            in[(size_t)(by + threadIdx.y + j) * C + bx + threadIdx.x];
    __syncthreads();
#pragma unroll
    for (int j = 0; j < 32; j += 8)
        out[(size_t)(bx + threadIdx.y + j) * R + by + threadIdx.x] =
            t[threadIdx.x][threadIdx.y + j];
}

// ---------------- fp16 GEMM mainloop (R15 scalar-LDS version) -----------------
#define WPITCH 20
#define TILE_W (128 * WPITCH)
#define GEMM_SMEM (2 * 2 * TILE_W * 4)

#define GEMM_MAINLOOP(Aptr, Bptr)                                              \
    float acc[4][4][4];                                                        \
    _Pragma("unroll")                                                          \
    for (int mi = 0; mi < 4; mi++)                                             \
        _Pragma("unroll")                                                      \
        for (int ni = 0; ni < 4; ni++)                                         \
            _Pragma("unroll")                                                  \
            for (int e = 0; e < 4; e++) acc[mi][ni][e] = 0.0f;                 \
    float4 av[4], bv[4];                                                       \
    _Pragma("unroll")                                                          \
    for (int p = 0; p < 4; p++) {                                              \
        int row = p * 32 + lrow;                                               \
        av[p] = *(const float4*)(Aptr + (size_t)row * GK + lc4);               \
        bv[p] = *(const float4*)(Bptr + (size_t)row * GK + lc4);               \
    }                                                                          \
    {                                                                          \
        uint32_t* As = smem;                                                   \
        uint32_t* Bs = smem + TILE_W;                                          \
        _Pragma("unroll")                                                      \
        for (int p = 0; p < 4; p++) {                                          \
            int row = p * 32 + lrow;                                           \
            uint32_t* ap = As + row * WPITCH + (lc4 >> 1);                     \
            ap[0] = f2h2(av[p].x, av[p].y);                                    \
            ap[1] = f2h2(av[p].z, av[p].w);                                    \
            uint32_t* bp = Bs + row * WPITCH + (lc4 >> 1);                     \
            bp[0] = f2h2(bv[p].x, bv[p].y);                                    \
            bp[1] = f2h2(bv[p].z, bv[p].w);                                    \
        }                                                                      \
    }                                                                          \
    __syncthreads();                                                           \
    for (int i = 0; i < NCHUNK; i++) {                                         \
        if (i + 1 < NCHUNK) {                                                  \
            int k0 = (i + 1) * CHUNK;                                          \
            _Pragma("unroll")                                                  \
            for (int p = 0; p < 4; p++) {                                      \
                int row = p * 32 + lrow;                                       \
                av[p] = *(const float4*)(Aptr + (size_t)row * GK + k0 + lc4);  \
                bv[p] = *(const float4*)(Bptr + (size_t)row * GK + k0 + lc4);  \
            }                                                                  \
        }                                                                      \
        {                                                                      \
            uint32_t* As = smem + (i & 1) * 2 * TILE_W;                        \
            uint32_t* Bs = As + TILE_W;                                        \
            _Pragma("unroll")                                                  \
            for (int ks = 0; ks < 2; ks++) {                                   \
                int kw = ks * 8;                                               \
                uint32_t afr[4][4];                                            \
                _Pragma("unroll")                                              \
                for (int mi = 0; mi < 4; mi++) {                               \
                    int r0 = wm + mi * 16 + g;                                 \
                    afr[mi][0] = As[r0 * WPITCH + kw + t];                     \
                    afr[mi][1] = As[(r0 + 8) * WPITCH + kw + t];               \
                    afr[mi][2] = As[r0 * WPITCH + kw + t + 4];                 \
                    afr[mi][3] = As[(r0 + 8) * WPITCH + kw + t + 4];           \
                }                                                              \
                uint32_t bfr[4][2];                                            \
                _Pragma("unroll")                                              \
                for (int ni = 0; ni < 4; ni++) {                               \
                    int n0 = wn + ni * 8 + g;                                  \
                    bfr[ni][0] = Bs[n0 * WPITCH + kw + t];                     \
                    bfr[ni][1] = Bs[n0 * WPITCH + kw + t + 4];                 \
                }                                                              \
                _Pragma("unroll")                                              \
                for (int mi = 0; mi < 4; mi++)                                 \
                    _Pragma("unroll")                                          \
                    for (int ni = 0; ni < 4; ni++)                             \
                        MMA_F16(acc[mi][ni], afr[mi], bfr[ni]);                \
            }                                                                  \
        }                                                                      \
        if (i + 1 < NCHUNK) {                                                  \
            __syncthreads();                                                   \
            uint32_t* As = smem + ((i + 1) & 1) * 2 * TILE_W;                  \
            uint32_t* Bs = As + TILE_W;                                        \
            _Pragma("unroll")                                                  \
            for (int p = 0; p < 4; p++) {                                      \
                int row = p * 32 + lrow;                                       \
                uint32_t* ap = As + row * WPITCH + (lc4 >> 1);                 \
                ap[0] = f2h2(av[p].x, av[p].y);                                \
                ap[1] = f2h2(av[p].z, av[p].w);                                \
                uint32_t* bp = Bs + row * WPITCH + (lc4 >> 1);                 \
                bp[0] = f2h2(bv[p].x, bv[p].y);                                \
                bp[1] = f2h2(bv[p].z, bv[p].w);                                \
            }                                                                  \
            __syncthreads();                                                   \
        }                                                                      \
    }

// ---------------- plain GEMM (output projection) ------------------------------
__global__ __launch_bounds__(256)
void f16_gemm(const float* __restrict__ A, const float* __restrict__ BT,
              float* __restrict__ C, int N) {
    extern __shared__ uint32_t smem[];
    int tid = threadIdx.x;
    int w = tid >> 5, lane = tid & 31;
    int g = lane >> 2, t = lane & 3;
    int wm = (w >> 2) * 64, wn = (w & 3) * 32;
    int bm = blockIdx.y * 128, bn = blockIdx.x * 128;
    const float* Ab = A + (size_t)bm * GK;
    const float* Bb = BT + (size_t)bn * GK;
    int lrow = tid >> 3, lc4 = (tid & 7) << 2;

    GEMM_MAINLOOP(Ab, Bb)

#pragma unroll
    for (int mi = 0; mi < 4; mi++) {
#pragma unroll
        for (int ni = 0; ni < 4; ni++) {
            int r0 = bm + wm + mi * 16 + g;
            int c0 = bn + wn + ni * 8 + t * 2;
            *(float2*)(C + (size_t)r0 * N + c0) =
                make_float2(acc[mi][ni][0], acc[mi][ni][1]);
            *(float2*)(C + (size_t)(r0 + 8) * N + c0) =
                make_float2(acc[mi][ni][2], acc[mi][ni][3]);
        }
    }
}

// ---------------- fused QKV GEMM + RoPE epilogue (fp16 Q/K/V^T out) -----------
#define QSCALE (0.125f * 1.44269504088896f)   // 1/sqrt(64) * log2(e)

__device__ __forceinline__ void qkv_write_pair(
    __half* gq, __half* gk, __half* gvt,
    const float* __restrict__ fc, const float* __restrict__ fs,
    int r, int c, float e0, float e1) {
    int b = r >> 11, s = r & 2047;
    if (c < HID) {
        int h = c >> 6, d = c & 63, p = d >> 1;
        float cs = fc[s * HALF + p], sn = fs[s * HALF + p];
        *(uint32_t*)(gq + ((size_t)(b * NH + h) * SEQ + s) * HD + d) =
            f2h2((e0 * cs - e1 * sn) * QSCALE, (e0 * sn + e1 * cs) * QSCALE);
    } else if (c < HID + NKV * HD) {
        int cc = c - HID;
        int kvh = cc >> 6, d = cc & 63, p = d >> 1;
        float cs = fc[s * HALF + p], sn = fs[s * HALF + p];
        *(uint32_t*)(gk + ((size_t)(b * NKV + kvh) * SEQ + s) * HD + d) =
            f2h2(e0 * cs - e1 * sn, e0 * sn + e1 * cs);
    } else {                                  // V: fp16 transposed [B,KV,D,S]
        int cc = c - HID - NKV * HD;
        int kvh = cc >> 6, d = cc & 63;
        size_t base = ((size_t)(b * NKV + kvh) * HD + d) * SEQ + s;
        gvt[base] = __float2half(e0);
        gvt[base + SEQ] = __float2half(e1);
    }
}

__global__ __launch_bounds__(256)
void qkv_rope_gemm(const float* __restrict__ A, const float* __restrict__ BT,
                   __half* gq, __half* gk, __half* gvt,
                   const float* __restrict__ fc, const float* __restrict__ fs) {
    extern __shared__ uint32_t smem[];
    int tid = threadIdx.x;
    int w = tid >> 5, lane = tid & 31;
    int g = lane >> 2, t = lane & 3;
    int wm = (w >> 2) * 64, wn = (w & 3) * 32;
    int bm = blockIdx.y * 128, bn = blockIdx.x * 128;
    const float* Ab = A + (size_t)bm * GK;
    const float* Bb = BT + (size_t)bn * GK;
    int lrow = tid >> 3, lc4 = (tid & 7) << 2;

    GEMM_MAINLOOP(Ab, Bb)

#pragma unroll
    for (int mi = 0; mi < 4; mi++) {
#pragma unroll
        for (int ni = 0; ni < 4; ni++) {
            int r0 = bm + wm + mi * 16 + g;
            int c0 = bn + wn + ni * 8 + t * 2;
            qkv_write_pair(gq, gk, gvt, fc, fs, r0, c0,
                           acc[mi][ni][0], acc[mi][ni][1]);
            qkv_write_pair(gq, gk, gvt, fc, fs, r0 + 8, c0,
                           acc[mi][ni][2], acc[mi][ni][3]);
        }
    }
}

// ---------------- fp16 flash attention, cp.async double-buffered --------------
// CTA: 128 q-rows x one (b,h), 8 warps x 16 rows, K-tile = 64 keys.
// K smem [key][64h] pitch 36 words (144B, 16B-aligned); V^T same; P per-warp.
#define AP 36
#define KBUF (64 * AP)                 // words per K or V buffer
#define PS_OFF (4 * KBUF)              // after K0,K1,V0,V1
#define ATTN_SMEM ((4 * KBUF + 8 * 16 * AP) * 4)   // 55296 B

__global__ __launch_bounds__(256, 2)
void attn_f16_kernel(const __half* __restrict__ Q, const __half* __restrict__ K,
                     const __half* __restrict__ Vt, float* __restrict__ O) {
    extern __shared__ uint32_t sm[];

    int tid = threadIdx.x;
    int w = tid >> 5, lane = tid & 31;
    int g = lane >> 2, t = lane & 3;
    int qt = gridDim.x - 1 - blockIdx.x;     // longest first
    int bh = blockIdx.y;
    int b = bh >> 5, h = bh & 31;
    int kvh = h >> 2;
    int q0 = qt * 128;
    int qrow = w * 16;

    uint32_t smbase = smem_u32(sm);
    uint32_t* Pw = sm + PS_OFF + w * 16 * AP;

    const __half* Qb = Q + ((size_t)(b * NH + h) * SEQ + q0) * HD;
    const __half* Kb = K + (size_t)(b * NKV + kvh) * SEQ * HD;
    const __half* Vb = Vt + (size_t)(b * NKV + kvh) * HD * SEQ;

    // Q fragments (already fp16 in global) -> registers once
    uint32_t qf[4][4];
#pragma unroll
    for (int ks = 0; ks < 4; ks++) {
        int d0 = ks * 16 + 2 * t;
        qf[ks][0] = *(const uint32_t*)(Qb + (qrow + g) * HD + d0);
        qf[ks][1] = *(const uint32_t*)(Qb + (qrow + 8 + g) * HD + d0);
        qf[ks][2] = *(const uint32_t*)(Qb + (qrow + g) * HD + d0 + 8);
        qf[ks][3] = *(const uint32_t*)(Qb + (qrow + 8 + g) * HD + d0 + 8);
    }

    float oacc[8][4];
#pragma unroll
    for (int ni = 0; ni < 8; ni++)
#pragma unroll
        for (int e = 0; e < 4; e++) oacc[ni][e] = 0.0f;
    float m0 = -1e30f, m1 = -1e30f, l0 = 0.0f, l1 = 0.0f;   // l: per-thread partial

    int ktmax = (q0 >> 6) + 1;

    // per-thread copy coords: 2 chunks each for K and V
    int c0r = tid >> 3, c0s = tid & 7;          // chunk tid
    int c1r = 32 + (tid >> 3), c1s = tid & 7;   // chunk tid+256

    // ---- prologue: stage tile 0 into buffer 0 ----
    {
        const __half* Kp = Kb;
        const __half* Vp = Vb;
        uint32_t kd = smbase;
        uint32_t vd = smbase + (2 * KBUF) * 4;
        CP_ASYNC16(kd + (c0r * AP + c0s * 4) * 4, Kp + c0r * HD + c0s * 8);
        CP_ASYNC16(kd + (c1r * AP + c1s * 4) * 4, Kp + c1r * HD + c1s * 8);
        CP_ASYNC16(vd + (c0r * AP + c0s * 4) * 4, Vp + (size_t)c0r * SEQ + c0s * 8);
        CP_ASYNC16(vd + (c1r * AP + c1s * 4) * 4, Vp + (size_t)c1r * SEQ + c1s * 8);
        CP_COMMIT();
    }

    for (int kt = 0; kt <= ktmax; kt++) {
        __syncthreads();   // alternate buffer fully consumed CTA-wide
        if (kt < ktmax) {  // stage tile kt+1 into alternate buffer
            int bb = (kt + 1) & 1;
            const __half* Kp = Kb + (size_t)(kt + 1) * 64 * HD;
            const __half* Vp = Vb + (size_t)(kt + 1) * 64;
            uint32_t kd = smbase + (bb * KBUF) * 4;
            uint32_t vd = smbase + ((2 + bb) * KBUF) * 4;
            CP_ASYNC16(kd + (c0r * AP + c0s * 4) * 4, Kp + c0r * HD + c0s * 8);
            CP_ASYNC16(kd + (c1r * AP + c1s * 4) * 4, Kp + c1r * HD + c1s * 8);
            CP_ASYNC16(vd + (c0r * AP + c0s * 4) * 4, Vp + (size_t)c0r * SEQ + c0s * 8);
            CP_ASYNC16(vd + (c1r * AP + c1s * 4) * 4, Vp + (size_t)c1r * SEQ + c1s * 8);
            CP_COMMIT();
            CP_WAIT(1);    // tile kt's group done (kt+1 may be in flight)
        } else {
            CP_WAIT(0);
        }
        __syncthreads();   // all threads' tile-kt data visible

        uint32_t* Ks = sm + (kt & 1) * KBUF;
        uint32_t* Vs = sm + (2 + (kt & 1)) * KBUF;

        // ---- S = Q K^T  (k-dim = d, 4 steps of 16) ----
        float sa[8][4];
#pragma unroll
        for (int ni = 0; ni < 8; ni++)
#pragma unroll
            for (int e = 0; e < 4; e++) sa[ni][e] = 0.0f;
#pragma unroll
        for (int ks = 0; ks < 4; ks++) {
            int kw = ks * 8;
#pragma unroll
            for (int ni = 0; ni < 8; ni++) {
                int n0 = ni * 8 + g;
                uint32_t bfr[2];
                bfr[0] = Ks[n0 * AP + kw + t];
                bfr[1] = Ks[n0 * AP + kw + t + 4];
                MMA_F16(sa[ni], qf[ks], bfr);
            }
        }

        // ---- causal mask ----
        int r0 = q0 + qrow + g, r1 = r0 + 8;
        if (kt * 64 + 63 > r0) {
            int cb = kt * 64;
#pragma unroll
            for (int ni = 0; ni < 8; ni++) {
                int c0 = cb + ni * 8 + 2 * t, c1 = c0 + 1;
                if (c0 > r0) sa[ni][0] = -1e30f;
                if (c1 > r0) sa[ni][1] = -1e30f;
                if (c0 > r1) sa[ni][2] = -1e30f;
                if (c1 > r1) sa[ni][3] = -1e30f;
            }
        }

        // ---- online softmax (log2 domain; per-thread partial l) ----
        float mx0 = -1e30f, mx1 = -1e30f;
#pragma unroll
        for (int ni = 0; ni < 8; ni++) {
            mx0 = fmaxf(mx0, fmaxf(sa[ni][0], sa[ni][1]));
            mx1 = fmaxf(mx1, fmaxf(sa[ni][2], sa[ni][3]));
        }
        mx0 = fmaxf(mx0, __shfl_xor_sync(0xffffffffu, mx0, 1));
        mx0 = fmaxf(mx0, __shfl_xor_sync(0xffffffffu, mx0, 2));
        mx1 = fmaxf(mx1, __shfl_xor_sync(0xffffffffu, mx1, 1));
        mx1 = fmaxf(mx1, __shfl_xor_sync(0xffffffffu, mx1, 2));
        float mn0 = fmaxf(m0, mx0), mn1 = fmaxf(m1, mx1);
        float sc0 = ex2(m0 - mn0), sc1 = ex2(m1 - mn1);
        m0 = mn0; m1 = mn1;
        float sum0 = 0.0f, sum1 = 0.0f;
#pragma unroll
        for (int ni = 0; ni < 8; ni++) {
            sa[ni][0] = ex2(sa[ni][0] - mn0); sum0 += sa[ni][0];
            sa[ni][1] = ex2(sa[ni][1] - mn0); sum0 += sa[ni][1];
            sa[ni][2] = ex2(sa[ni][2] - mn1); sum1 += sa[ni][2];
            sa[ni][3] = ex2(sa[ni][3] - mn1); sum1 += sa[ni][3];
        }
        l0 = l0 * sc0 + sum0;
        l1 = l1 * sc1 + sum1;
#pragma unroll
        for (int ni = 0; ni < 8; ni++) {
            oacc[ni][0] *= sc0; oacc[ni][1] *= sc0;
            oacc[ni][2] *= sc1; oacc[ni][3] *= sc1;
        }

        // ---- P -> packed halves [16 rows][32 words], per-warp region ----
#pragma unroll
        for (int ni = 0; ni < 8; ni++) {
            int c = 4 * ni + t;
            Pw[g * AP + c]       = f2h2(sa[ni][0], sa[ni][1]);
            Pw[(g + 8) * AP + c] = f2h2(sa[ni][2], sa[ni][3]);
        }
        __syncwarp();

        // ---- O += P V  (k-dim = key, 4 steps of 16) ----
#pragma unroll
        for (int ks = 0; ks < 4; ks++) {
            int kw = ks * 8;
            uint32_t a[4];
            a[0] = Pw[g * AP + kw + t];
            a[1] = Pw[(g + 8) * AP + kw + t];
            a[2] = Pw[g * AP + kw + t + 4];
            a[3] = Pw[(g + 8) * AP + kw + t + 4];
#pragma unroll
            for (int ni = 0; ni < 8; ni++) {
                int n0 = ni * 8 + g;     // d index -> Vs row
                uint32_t bfr[2];
                bfr[0] = Vs[n0 * AP + kw + t];
                bfr[1] = Vs[n0 * AP + kw + t + 4];
                MMA_F16(oacc[ni], a, bfr);
            }
        }
        __syncwarp();
    }

    // ---- final l reduction + normalize + write [B,S,H*D] ----
    l0 += __shfl_xor_sync(0xffffffffu, l0, 1);
    l0 += __shfl_xor_sync(0xffffffffu, l0, 2);
    l1 += __shfl_xor_sync(0xffffffffu, l1, 1);
    l1 += __shfl_xor_sync(0xffffffffu, l1, 2);
    float rl0 = 1.0f / l0, rl1 = 1.0f / l1;
    int r0 = q0 + qrow + g, r1 = r0 + 8;
#pragma unroll
    for (int ni = 0; ni < 8; ni++) {
        int col = ni * 8 + 2 * t;
        *(float2*)(O + ((size_t)(b * SEQ + r0) * NH + h) * HD + col) =
            make_float2(oacc[ni][0] * rl0, oacc[ni][1] * rl0);
        *(float2*)(O + ((size_t)(b * SEQ + r1) * NH + h) * HD + col) =
            make_float2(oacc[ni][2] * rl1, oacc[ni][3] * rl1);
    }
}

// ---------------- launcher ---------------------------------------------------
extern "C" void kernel_launch(void* const* d_in, const int* in_sizes, int n_in,
                              void* d_out, int out_size) {
    const float* x  = (const float*)d_in[0];
    const float* wq = (const float*)d_in[1];
    const float* wk = (const float*)d_in[2];
    const float* wv = (const float*)d_in[3];
    const float* wo = (const float*)d_in[4];
    const float* fc = (const float*)d_in[5];
    const float* fs = (const float*)d_in[6];
    float* out = (float*)d_out;

    __half *q, *k, *vt;
    float *ao, *wqkvT, *woT;
    cudaGetSymbolAddress((void**)&q,  g_q);
    cudaGetSymbolAddress((void**)&k,  g_k);
    cudaGetSymbolAddress((void**)&vt, g_vt);
    cudaGetSymbolAddress((void**)&ao, g_ao);
    cudaGetSymbolAddress((void**)&wqkvT, g_wqkvT);
    cudaGetSymbolAddress((void**)&woT, g_woT);

    const int M = BATCH * SEQ;  // 4096

    transpose_kernel<<<dim3(HID / 32, HID / 32), dim3(32, 8)>>>(wq, wqkvT, HID, HID);
    transpose_kernel<<<dim3((NKV * HD) / 32, HID / 32), dim3(32, 8)>>>(
        wk, wqkvT + (size_t)HID * HID, HID, NKV * HD);
    transpose_kernel<<<dim3((NKV * HD) / 32, HID / 32), dim3(32, 8)>>>(
        wv, wqkvT + (size_t)(HID + NKV * HD) * HID, HID, NKV * HD);
    transpose_kernel<<<dim3(HID / 32, HID / 32), dim3(32, 8)>>>(wo, woT, HID, HID);

    cudaFuncSetAttribute(qkv_rope_gemm, cudaFuncAttributeMaxDynamicSharedMemorySize,
                         GEMM_SMEM);
    cudaFuncSetAttribute(f16_gemm, cudaFuncAttributeMaxDynamicSharedMemorySize,
                         GEMM_SMEM);

    // fused QKV projection + RoPE epilogue (fp16 Q/K/V^T)
    qkv_rope_gemm<<<dim3(NQKV / 128, M / 128), 256, GEMM_SMEM>>>(
        x, wqkvT, q, k, vt, fc, fs);

    // fp16 flash attention with cp.async double buffering
    cudaFuncSetAttribute(attn_f16_kernel, cudaFuncAttributeMaxDynamicSharedMemorySize,
                         ATTN_SMEM);
    attn_f16_kernel<<<dim3(SEQ / 128, BATCH * NH), 256, ATTN_SMEM>>>(q, k, vt, ao);

    // output projection
    f16_gemm<<<dim3(HID / 128, M / 128), 256, GEMM_SMEM>>>(ao, woT, out, HID);
}